// round 17
// baseline (speedup 1.0000x reference)
#include <cuda_runtime.h>
#include <cuda_bf16.h>
#include <cstdint>

#define Bb 64
#define Nn 64
#define KDIM 512
#define NOUT 480           // NT*SEM = 30*16
#define NT 30
#define ROWS 4096
#define NSPAN 2016
#define NP1 65

// Scratch — __device__ globals (no allocation allowed)
__device__ float g_prefix[Bb * NP1 * NOUT];        // 7.99 MB
__device__ __nv_bfloat16 g_ahi[ROWS * KDIM];       // 4 MB
__device__ __nv_bfloat16 g_alo[ROWS * KDIM];       // 4 MB
__device__ __nv_bfloat16 g_whi[NOUT * KDIM];       // 0.5 MB
__device__ __nv_bfloat16 g_wlo[NOUT * KDIM];       // 0.5 MB

__device__ __forceinline__ void split2(float x, float y, unsigned& hi, unsigned& lo) {
    // hi = {bf16(y), bf16(x)} with x in low half
    asm("cvt.rn.bf16x2.f32 %0, %1, %2;" : "=r"(hi) : "f"(y), "f"(x));
    const float rx = x - __uint_as_float(hi << 16);
    const float ry = y - __uint_as_float(hi & 0xffff0000u);
    asm("cvt.rn.bf16x2.f32 %0, %1, %2;" : "=r"(lo) : "f"(ry), "f"(rx));
}

// ---------------------------------------------------------------------------
// Kernel 0: gather + hi/lo split of A (emb[x]) and W into bf16 buffers.
// ---------------------------------------------------------------------------
__global__ __launch_bounds__(256) void prep_kernel(
    const int* __restrict__ x, const float* __restrict__ emb,
    const float* __restrict__ w)
{
    const int blk = blockIdx.x;
    const int tid = threadIdx.x;
    const bool isA = (blk < 512);
    const int rbase = (isA ? blk : (blk - 512)) * 8;

#pragma unroll
    for (int i = 0; i < 4; i++) {
        const int idx = tid + i * 256;
        const int r8 = idx >> 7;
        const int pos = idx & 127;
        const int row = rbase + r8;
        const float* src;
        __nv_bfloat16 *dh, *dl;
        if (isA) {
            src = emb + (size_t)x[row] * KDIM + pos * 4;
            dh = g_ahi + (size_t)row * KDIM + pos * 4;
            dl = g_alo + (size_t)row * KDIM + pos * 4;
        } else {
            src = w + (size_t)row * KDIM + pos * 4;
            dh = g_whi + (size_t)row * KDIM + pos * 4;
            dl = g_wlo + (size_t)row * KDIM + pos * 4;
        }
        const float4 v = *(const float4*)src;
        uint2 h, l;
        split2(v.x, v.y, h.x, l.x);
        split2(v.z, v.w, h.y, l.y);
        *(uint2*)dh = h;
        *(uint2*)dl = l;
    }
}

// ---------------------------------------------------------------------------
// Kernel 1: bf16 hi/lo tensor GEMM + FUSED masked cumsum -> g_prefix.
// ---------------------------------------------------------------------------
#define BM 128
#define BN 48
#define BK 32
#define PITCH 40
#define ABUF_B (BM * PITCH * 2)  // 10240
#define BBUF_B (BN * PITCH * 2)  // 3840
#define AHI_B 0
#define ALO_B ABUF_B
#define BHI_B (2 * ABUF_B)
#define BLO_B (2 * ABUF_B + BBUF_B)
#define STAGE_B (2 * ABUF_B + 2 * BBUF_B)   // 28160
#define SMEM_DYN (2 * STAGE_B)              // 56320
#define NKT (KDIM / BK)                     // 16
#define SPITCH 50

__device__ __forceinline__ uint32_t s2u(const void* p) {
    uint32_t a;
    asm("{ .reg .u64 t; cvta.to.shared.u64 t, %1; cvt.u32.u64 %0, t; }"
        : "=r"(a) : "l"(p));
    return a;
}

#define CPA16(dst, src)                                                   \
    asm volatile("cp.async.ca.shared.global [%0], [%1], 16;"              \
                 :: "r"(dst), "l"(src) : "memory")

#define LDSM4(r0, r1, r2, r3, addr)                                       \
    asm volatile("ldmatrix.sync.aligned.m8n8.x4.shared.b16 "              \
                 "{%0,%1,%2,%3}, [%4];"                                   \
                 : "=r"(r0), "=r"(r1), "=r"(r2), "=r"(r3) : "r"(addr))

#define LDSM2(r0, r1, addr)                                               \
    asm volatile("ldmatrix.sync.aligned.m8n8.x2.shared.b16 "              \
                 "{%0,%1}, [%2];"                                         \
                 : "=r"(r0), "=r"(r1) : "r"(addr))

#define MMA_BF16(c, a, b0_, b1_)                                          \
    asm volatile(                                                         \
        "mma.sync.aligned.m16n8k16.row.col.f32.bf16.bf16.f32 "            \
        "{%0,%1,%2,%3}, {%4,%5,%6,%7}, {%8,%9}, {%0,%1,%2,%3};"           \
        : "+f"((c)[0]), "+f"((c)[1]), "+f"((c)[2]), "+f"((c)[3])          \
        : "r"((a)[0]), "r"((a)[1]), "r"((a)[2]), "r"((a)[3]),             \
          "r"(b0_), "r"(b1_))

__global__ __launch_bounds__(256, 2) void gemm_kernel(
    const float* __restrict__ bo, const int* __restrict__ lengths)
{
    extern __shared__ __align__(16) char smem[];
    const uint32_t sbase = s2u(smem);

    const int tid = threadIdx.x;
    const int m0 = blockIdx.x * BM;
    const int n0 = blockIdx.y * BN;

    const int lane = tid & 31;
    const int grp = lane >> 2;
    const int qid = lane & 3;
    const int warpid = tid >> 5;
    const int wm = warpid & 3;
    const int wn = warpid >> 2;

    const int ac0 = tid, ac1 = tid + 256;
    const __nv_bfloat16* ah_src0 = g_ahi + (size_t)(m0 + (ac0 >> 2)) * KDIM + (ac0 & 3) * 8;
    const __nv_bfloat16* ah_src1 = g_ahi + (size_t)(m0 + (ac1 >> 2)) * KDIM + (ac1 & 3) * 8;
    const __nv_bfloat16* al_src0 = g_alo + (size_t)(m0 + (ac0 >> 2)) * KDIM + (ac0 & 3) * 8;
    const __nv_bfloat16* al_src1 = g_alo + (size_t)(m0 + (ac1 >> 2)) * KDIM + (ac1 & 3) * 8;
    const uint32_t a_dst0 = (ac0 >> 2) * 80 + (ac0 & 3) * 16;
    const uint32_t a_dst1 = (ac1 >> 2) * 80 + (ac1 & 3) * 16;
    const bool hasB = (tid < 192);
    const int bc = hasB ? tid : 0;
    const __nv_bfloat16* bh_src = g_whi + (size_t)(n0 + (bc >> 2)) * KDIM + (bc & 3) * 8;
    const __nv_bfloat16* bl_src = g_wlo + (size_t)(n0 + (bc >> 2)) * KDIM + (bc & 3) * 8;
    const uint32_t b_dst = (bc >> 2) * 80 + (bc & 3) * 16;

#define CP_STAGE(ST, KT)                                                       \
    do {                                                                       \
        const int ko = (KT) * BK;                                              \
        const uint32_t sb = sbase + (ST) * STAGE_B;                            \
        CPA16(sb + AHI_B + a_dst0, ah_src0 + ko);                              \
        CPA16(sb + AHI_B + a_dst1, ah_src1 + ko);                              \
        CPA16(sb + ALO_B + a_dst0, al_src0 + ko);                              \
        CPA16(sb + ALO_B + a_dst1, al_src1 + ko);                              \
        if (hasB) {                                                            \
            CPA16(sb + BHI_B + b_dst, bh_src + ko);                            \
            CPA16(sb + BLO_B + b_dst, bl_src + ko);                            \
        }                                                                      \
        asm volatile("cp.async.commit_group;" ::: "memory");                   \
    } while (0)

    const int lt = lane >> 3, lr = lane & 7;
    const uint32_t a_off = (uint32_t)((wm * 32 + (lt & 1) * 8 + lr) * 80 + (lt >> 1) * 16);
    const uint32_t b4_off = (uint32_t)((wn * 24 + (lt >> 1) * 8 + lr) * 80 + (lt & 1) * 16);
    const int l15 = lane & 15;
    const uint32_t b2_off = (uint32_t)((wn * 24 + 16 + (l15 & 7)) * 80 + ((l15 >> 3) & 1) * 16);

    float acc[2][3][4];
#pragma unroll
    for (int ma = 0; ma < 2; ma++)
#pragma unroll
        for (int j = 0; j < 3; j++)
#pragma unroll
            for (int c = 0; c < 4; c++) acc[ma][j][c] = 0.0f;

#define COMPUTE(ST)                                                            \
    do {                                                                       \
        const uint32_t sb = sbase + (ST) * STAGE_B;                            \
        _Pragma("unroll")                                                      \
        for (int kb = 0; kb < BK; kb += 16) {                                  \
            unsigned ah[2][4], al[2][4], bh[3][2], bl[3][2];                   \
            _Pragma("unroll")                                                  \
            for (int ma = 0; ma < 2; ma++) {                                   \
                const uint32_t aa = sb + a_off + ma * 1280 + kb * 2;           \
                LDSM4(ah[ma][0], ah[ma][1], ah[ma][2], ah[ma][3], aa + AHI_B); \
                LDSM4(al[ma][0], al[ma][1], al[ma][2], al[ma][3], aa + ALO_B); \
            }                                                                  \
            {                                                                  \
                const uint32_t b4 = sb + b4_off + kb * 2;                      \
                const uint32_t b2 = sb + b2_off + kb * 2;                      \
                LDSM4(bh[0][0], bh[0][1], bh[1][0], bh[1][1], b4 + BHI_B);     \
                LDSM2(bh[2][0], bh[2][1], b2 + BHI_B);                         \
                LDSM4(bl[0][0], bl[0][1], bl[1][0], bl[1][1], b4 + BLO_B);     \
                LDSM2(bl[2][0], bl[2][1], b2 + BLO_B);                         \
            }                                                                  \
            _Pragma("unroll")                                                  \
            for (int ma = 0; ma < 2; ma++)                                     \
                _Pragma("unroll")                                              \
                for (int j = 0; j < 3; j++) {                                  \
                    MMA_BF16(acc[ma][j], ah[ma], bh[j][0], bh[j][1]);          \
                    MMA_BF16(acc[ma][j], ah[ma], bl[j][0], bl[j][1]);          \
                    MMA_BF16(acc[ma][j], al[ma], bh[j][0], bh[j][1]);          \
                }                                                              \
        }                                                                      \
    } while (0)

    CP_STAGE(0, 0);
    asm volatile("cp.async.wait_group 0;" ::: "memory");
    __syncthreads();

#pragma unroll 1
    for (int kt = 0; kt < NKT; kt++) {
        if (kt < NKT - 1) CP_STAGE((kt + 1) & 1, kt + 1);
        COMPUTE(kt & 1);
        asm volatile("cp.async.wait_group 0;" ::: "memory");
        __syncthreads();
    }

    // ---- Fused epilogue: stage acc -> smem, then masked cumsum -> g_prefix
    float* stage = (float*)smem;   // [128][SPITCH]
#pragma unroll
    for (int j = 0; j < 3; j++) {
        const int col = wn * 24 + j * 8 + qid * 2;
#pragma unroll
        for (int ma = 0; ma < 2; ma++) {
            const int r0 = wm * 32 + ma * 16 + grp;
            stage[r0 * SPITCH + col]           = acc[ma][j][0];
            stage[r0 * SPITCH + col + 1]       = acc[ma][j][1];
            stage[(r0 + 8) * SPITCH + col]     = acc[ma][j][2];
            stage[(r0 + 8) * SPITCH + col + 1] = acc[ma][j][3];
        }
    }
    __syncthreads();

    if (tid < 96) {
        const int bb = tid / 48;
        const int col = tid % 48;
        const int batch = (m0 >> 6) + bb;
        const int len = lengths[batch];
        const int gcol = n0 + col;
        const float bias = bo[gcol];
        float accu = 0.0f;
        float* gp = g_prefix + (size_t)(batch * NP1) * NOUT + gcol;
        gp[0] = 0.0f;
#pragma unroll 4
        for (int n = 0; n < Nn; n++) {
            const float v = stage[(bb * Nn + n) * SPITCH + col] + bias;
            if (n < len) accu += v;
            gp[(size_t)(n + 1) * NOUT] = accu;
        }
    }
}

// ---------------------------------------------------------------------------
// Kernel 3: span features + L2 norm, smem-tiled over 8x8 (l, r) tiles.
// One thread per (span, nt) group: L row cached in registers (li = tid/30,
// fixed per thread), 8 R rows iterated. Groups padded to 5 float4 in smem
// (stride-5 mod 8 bijection -> conflict-free). No shfl, .cs stores.
// ---------------------------------------------------------------------------
#define STH 256
#define GPAD 20      // floats per nt group in smem (5 float4)
#define SROW (NT * GPAD)   // 600 floats per row

#define STG_CS4(ptr, v)                                                       \
    asm volatile("st.global.cs.v4.f32 [%0], {%1,%2,%3,%4};"                   \
                 :: "l"(ptr), "f"((v).x), "f"((v).y), "f"((v).z), "f"((v).w)  \
                 : "memory")

__global__ __launch_bounds__(STH, 4) void span_kernel(float* __restrict__ out)
{
    __shared__ float sL[8][SROW];
    __shared__ float sR[8][SROW];

    const int b = blockIdx.y;
    const int t = blockIdx.x;                 // 0..35, t = rt*(rt+1)/2 + lt
    int rt = 0;
    while ((rt + 1) * (rt + 2) / 2 <= t) rt++;
    const int lt = t - rt * (rt + 1) / 2;

    const int tid = threadIdx.x;
    const float* pb = g_prefix + (size_t)b * NP1 * NOUT;

    // load 16 rows x 120 float4, padded-group layout
    for (int i4 = tid; i4 < 16 * (NOUT / 4); i4 += STH) {
        const int row = i4 / (NOUT / 4);
        const int q = i4 % (NOUT / 4);
        const int grow = (row < 8) ? (lt * 8 + row) : (rt * 8 + (row - 8) + 1);
        const float4 v = *(const float4*)(pb + (size_t)grow * NOUT + q * 4);
        const int spos = (q >> 2) * GPAD + (q & 3) * 4;
        if (row < 8) *(float4*)&sL[row][spos] = v;
        else         *(float4*)&sR[row - 8][spos] = v;
    }
    __syncthreads();

    if (tid < 240) {
        const int li = tid / NT;          // fixed left row 0..7
        const int nt = tid - li * NT;     // 0..29
        const bool diag = (lt == rt);
        const int l = lt * 8 + li;

        // preload L group into registers
        float4 lv[4];
#pragma unroll
        for (int j = 0; j < 4; j++)
            lv[j] = *(const float4*)&sL[li][nt * GPAD + j * 4];

#pragma unroll 4
        for (int i = 0; i < 8; i++) {     // right row index
            float4 d[4];
            float sq = 0.0f;
#pragma unroll
            for (int j = 0; j < 4; j++) {
                const float4 rv = *(const float4*)&sR[i][nt * GPAD + j * 4];
                d[j].x = rv.x - lv[j].x;
                d[j].y = rv.y - lv[j].y;
                d[j].z = rv.z - lv[j].z;
                d[j].w = rv.w - lv[j].w;
                sq = fmaf(d[j].x, d[j].x, sq);
                sq = fmaf(d[j].y, d[j].y, sq);
                sq = fmaf(d[j].z, d[j].z, sq);
                sq = fmaf(d[j].w, d[j].w, sq);
            }
            const float inv = rsqrtf(sq);

            if (!diag || li < i) {
                const int r = rt * 8 + i;
                const int k = r - l;
                const int s = (((k - 1) * (128 - k)) >> 1) + l;
                float* op = out + ((size_t)(b * NSPAN + s) * NT + nt) * 16;
#pragma unroll
                for (int j = 0; j < 4; j++) {
                    float4 o;
                    o.x = d[j].x * inv;
                    o.y = d[j].y * inv;
                    o.z = d[j].z * inv;
                    o.w = d[j].w * inv;
                    STG_CS4(op + j * 4, o);
                }
            }
        }
    }
}

// ---------------------------------------------------------------------------
extern "C" void kernel_launch(void* const* d_in, const int* in_sizes, int n_in,
                              void* d_out, int out_size)
{
    const int*   x       = (const int*)d_in[0];
    const int*   lengths = (const int*)d_in[1];
    const float* emb     = (const float*)d_in[2];
    const float* w_out   = (const float*)d_in[3];
    const float* b_out   = (const float*)d_in[4];
    float* out = (float*)d_out;

    cudaFuncSetAttribute(gemm_kernel,
                         cudaFuncAttributeMaxDynamicSharedMemorySize, SMEM_DYN);

    prep_kernel<<<572, 256>>>(x, emb, w_out);
    gemm_kernel<<<dim3(ROWS / BM, NOUT / BN), 256, SMEM_DYN>>>(b_out, lengths);
    span_kernel<<<dim3(36, Bb), STH>>>(out);
}